// round 15
// baseline (speedup 1.0000x reference)
#include <cuda_runtime.h>
#include <cuda_fp16.h>
#include <math.h>
#include <stdint.h>

// ---------------- problem constants ----------------
#define Bz   16
#define T0   400
#define F0c  40
#define Hc   512
#define T1c  396
#define T3c  384
#define Kbot (Hc*Hc)   // 262144
#define OFF2 (Bz*Hc*T1c)

// weight arena offsets (elements)
#define WO1 0
#define WO2 102400
#define WO3 888832
#define WO4 1675264
#define WO5 1937408
#define WTOT 2199552

// ---------------- scratch ----------------
__device__ float g_bufA[Bz*Hc*T1c];          // raw fp32 GEMM outputs (conv1/lin4)
__device__ float g_buf2[2*Bz*Hc*T1c];        // split-K halves / lin5 raw out
__device__ uint32_t g_act[Bz*Hc*T1c];        // packed (lo16|hi16) split activations
__device__ __half g_wH[WTOT];
__device__ __half g_wL[WTOT];
__device__ __half g_x5H[Bz*Hc*T3c];
__device__ __half g_x5L[Bz*Hc*T3c];
__device__ uint32_t g_M[Bz*Kbot];            // pooled matrices, packed
__device__ float g_sums[5][Hc];
__device__ float g_sumsqs[5][Hc];
__device__ float g_h[Bz*Hc];
__device__ float g_zero[Hc];

// ---------------- helpers ----------------
__device__ __forceinline__ float relu20(float v)
{
    return fminf(fmaxf(v, 0.f), 20.f);
}

__device__ __forceinline__ uint32_t f16_split_pack(float v)
{
    __half h = __float2half_rn(v);
    __half l = __float2half_rn(v - __half2float(h));
    return ((uint32_t)__half_as_ushort(l) << 16) | (uint32_t)__half_as_ushort(h);
}

__device__ __forceinline__ void f16_split2(float x0, float x1, uint32_t& hw, uint32_t& lw)
{
    __half2 h = __floats2half2_rn(x0, x1);
    float2 hf = __half22float2(h);
    __half2 l = __floats2half2_rn(x0 - hf.x, x1 - hf.y);
    hw = *(uint32_t*)&h;
    lw = *(uint32_t*)&l;
}

__device__ __forceinline__ void mma_f16_k16(float* d, const uint32_t* a, const uint32_t* b)
{
    asm volatile(
        "mma.sync.aligned.m16n8k16.row.col.f32.f16.f16.f32 "
        "{%0,%1,%2,%3}, {%4,%5,%6,%7}, {%8,%9}, {%0,%1,%2,%3};"
        : "+f"(d[0]), "+f"(d[1]), "+f"(d[2]), "+f"(d[3])
        : "r"(a[0]), "r"(a[1]), "r"(a[2]), "r"(a[3]), "r"(b[0]), "r"(b[1]));
}

__device__ __forceinline__ void ldsm_x4(uint32_t* r, uint32_t saddr)
{
    asm volatile("ldmatrix.sync.aligned.m8n8.x4.shared.b16 {%0,%1,%2,%3}, [%4];"
        : "=r"(r[0]), "=r"(r[1]), "=r"(r[2]), "=r"(r[3]) : "r"(saddr));
}

__device__ __forceinline__ void sts_v2(uint32_t saddr, uint32_t v0, uint32_t v1)
{
    asm volatile("st.shared.v2.u32 [%0], {%1,%2};" :: "r"(saddr), "r"(v0), "r"(v1));
}

__device__ __forceinline__ void cp_async16(uint32_t saddr, const void* gaddr)
{
    asm volatile("cp.async.cg.shared.global [%0], [%1], 16;"
        :: "r"(saddr), "l"(gaddr));
}
#define CP_COMMIT() asm volatile("cp.async.commit_group;")
#define CP_WAIT1()  asm volatile("cp.async.wait_group 1;")

// ---------------- prep ----------------
__global__ void prep(const float* __restrict__ in,
                     const float* __restrict__ w1, const float* __restrict__ w2,
                     const float* __restrict__ w3, const float* __restrict__ w4,
                     const float* __restrict__ w5)
{
    int i = blockIdx.x * blockDim.x + threadIdx.x;
    if (i < WTOT) {
        float v;
        if (i < WO2)      v = w1[i];
        else if (i < WO3) v = w2[i - WO2];
        else if (i < WO4) v = w3[i - WO3];
        else if (i < WO5) v = w4[i - WO4];
        else              v = w5[i - WO5];
        __half h = __float2half_rn(v);
        g_wH[i] = h;
        g_wL[i] = __float2half_rn(v - __half2float(h));
    }
    if (i < Bz * T0 * F0c) {
        int c = i % F0c;
        int t = (i / F0c) % T0;
        int b = i / (F0c * T0);
        g_act[(b * F0c + c) * T0 + t] = f16_split_pack(in[i]);
    }
    if (i < 5 * Hc) {
        (&g_sums[0][0])[i] = 0.f;
        (&g_sumsqs[0][0])[i] = 0.f;
    }
    if (i < Bz * Hc) {
        g_h[i] = 0.f;
    }
}

// ---------------- stats over two split-K halves (bias folded algebraically) ----------
__global__ __launch_bounds__(256)
void stats2(const float* __restrict__ Y0, const float* __restrict__ Y1,
            const float* __restrict__ bias,
            float* __restrict__ oSum, float* __restrict__ oSumsq, int T)
{
    const int c = blockIdx.x;          // 512 blocks, one channel each
    float s = 0.f, q = 0.f;
    for (int i = threadIdx.x; i < Bz * T; i += 256) {
        int b = i / T, t = i - b * T;
        size_t idx = ((size_t)b * Hc + c) * T + t;
        float v = Y0[idx] + Y1[idx];
        s += v; q += v * v;
    }
    __shared__ float rs[256], rq[256];
    rs[threadIdx.x] = s; rq[threadIdx.x] = q;
    __syncthreads();
    for (int st = 128; st > 0; st >>= 1) {
        if (threadIdx.x < st) {
            rs[threadIdx.x] += rs[threadIdx.x + st];
            rq[threadIdx.x] += rq[threadIdx.x + st];
        }
        __syncthreads();
    }
    if (threadIdx.x == 0) {
        float bb = bias[c];
        float N = (float)(Bz * T);
        float S = rs[0], Q = rq[0];
        oSum[c]   = S + N * bb;                    // sum of (y + bias)
        oSumsq[c] = Q + 2.f * bb * S + N * bb * bb;
    }
}

// ---------------- BN finalize+apply on two halves -> packed ----------------
__global__ __launch_bounds__(512)
void split_bn2(const float* __restrict__ Y0, const float* __restrict__ Y1,
               const float* __restrict__ bias, uint32_t* __restrict__ dst,
               const float* __restrict__ sums, const float* __restrict__ sumsqs,
               const float* __restrict__ gamma, const float* __restrict__ beta,
               float invN, int T, int total)
{
    __shared__ float sSc[Hc];
    __shared__ float sSh[Hc];
    {
        int c = threadIdx.x;
        float s = sums[c], q = sumsqs[c];
        float m = s * invN;
        float var = q * invN - m * m;
        float a = gamma[c] * rsqrtf(var + 1e-5f);
        sSc[c] = a;
        sSh[c] = beta[c] - a * m + a * bias[c];   // bias folded into shift
    }
    __syncthreads();
    for (int idx = blockIdx.x * 512 + threadIdx.x; idx < total; idx += gridDim.x * 512) {
        int c = (idx / T) & (Hc - 1);
        float v = relu20(sSc[c] * (Y0[idx] + Y1[idx]) + sSh[c]);
        __half h = __float2half_rn(v);
        __half l = __float2half_rn(v - __half2float(h));
        dst[idx] = ((uint32_t)__half_as_ushort(l) << 16) | (uint32_t)__half_as_ushort(h);
    }
}

// ---------------- BN finalize+apply+clamp+split (single buffer) ----------------
template<bool SEP>
__global__ __launch_bounds__(512)
void split_bn(const float* __restrict__ Y, uint32_t* __restrict__ dst,
              __half* __restrict__ dH, __half* __restrict__ dL,
              const float* __restrict__ sums, const float* __restrict__ sumsqs,
              const float* __restrict__ gamma, const float* __restrict__ beta,
              float invN, int T, int total)
{
    __shared__ float sSc[Hc];
    __shared__ float sSh[Hc];
    {
        int c = threadIdx.x;
        float s = sums[c], q = sumsqs[c];
        float m = s * invN;
        float var = q * invN - m * m;
        float a = gamma[c] * rsqrtf(var + 1e-5f);
        sSc[c] = a;
        sSh[c] = beta[c] - a * m;
    }
    __syncthreads();
    for (int idx = blockIdx.x * 512 + threadIdx.x; idx < total; idx += gridDim.x * 512) {
        int c = (idx / T) & (Hc - 1);
        float v = relu20(sSc[c] * Y[idx] + sSh[c]);
        __half h = __float2half_rn(v);
        __half l = __float2half_rn(v - __half2float(h));
        if (SEP) {
            dH[idx] = h;
            dL[idx] = l;
        } else {
            dst[idx] = ((uint32_t)__half_as_ushort(l) << 16) | (uint32_t)__half_as_ushort(h);
        }
    }
}

// ---------------- FP16x3 conv-as-GEMM (R13 structure + ldA for split-K) ----------
// A: pre-split fp16 hi/lo planes, cp.async 3-stage; row stride ldA (>= CK iter bound).
// X: packed (lo16|hi16) uint32 activations, im2col gather at prefetch distance 2.
// blockIdx.z: batch (pooling) or K-half (split-K) via strideA/strideX/strideY offsets.
#define RSTR 12
#define ASTG_B (128 * RSTR * 4)
#define BSTG_B (64 * RSTR * 4)
template<int KW, int DIL, bool STATS, bool PACK>
__global__ __launch_bounds__(256, 3)
void conv_gemm(const __half* __restrict__ AH, const __half* __restrict__ AL,
               const float* __restrict__ bias,
               const uint32_t* __restrict__ X, float* __restrict__ Y,
               float* __restrict__ oSum, float* __restrict__ oSumsq,
               int C, int Tin, int Tout, int CK, int ldA, int Ntot,
               int strideA, int strideX, int strideY)
{
    AH += (size_t)blockIdx.z * strideA;
    AL += (size_t)blockIdx.z * strideA;
    X  += (size_t)blockIdx.z * strideX;
    Y  += (size_t)blockIdx.z * strideY;

    __shared__ uint32_t AsH[3][128][RSTR];
    __shared__ uint32_t AsL[3][128][RSTR];
    __shared__ uint32_t BsH[2][64][RSTR];
    __shared__ uint32_t BsL[2][64][RSTR];

    const int tid  = threadIdx.x;
    const int lane = tid & 31;
    const int warp = tid >> 5;
    const int wm = warp >> 1;
    const int wn = warp & 1;
    const int oBase = blockIdx.y * 128;
    const int nBase = blockIdx.x * 64;

    float acc[2][4][4];
    #pragma unroll
    for (int i = 0; i < 2; i++)
        #pragma unroll
        for (int j = 0; j < 4; j++)
            #pragma unroll
            for (int r = 0; r < 4; r++) acc[i][j][r] = 0.f;

    const int aRow = tid >> 1;
    const int bN  = tid & 63;
    const int bG  = tid >> 6;

    const int nIdx = nBase + bN;
    const bool nValid = (nIdx < Ntot);
    int nb = 0, nt0 = 0;
    if (nValid) { nb = nIdx / Tout; nt0 = nIdx - nb * Tout; }
    const uint32_t* Xbase = X + ((size_t)nb * C) * Tin + nt0;
    const __half* ArowH = AH + (size_t)(oBase + aRow) * ldA + (tid & 1) * 8;
    const __half* ArowL = AL + (size_t)(oBase + aRow) * ldA + (tid & 1) * 8;

    const uint32_t baseAH = (uint32_t)__cvta_generic_to_shared(&AsH[0][0][0]);
    const uint32_t baseAL = (uint32_t)__cvta_generic_to_shared(&AsL[0][0][0]);
    const uint32_t baseBH = (uint32_t)__cvta_generic_to_shared(&BsH[0][0][0]);
    const uint32_t baseBL = (uint32_t)__cvta_generic_to_shared(&BsL[0][0][0]);

    const uint32_t stA = (aRow * RSTR + (tid & 1) * 4) * 4;
    const uint32_t stB = (bN * RSTR + bG * 2) * 4;

    const int aFragRow = (lane & 7) + ((lane >> 3) & 1) * 8;
    const int aFragWord = (lane >> 4) * 4;
    const uint32_t ldA0 = ((wm * 32 + aFragRow) * RSTR + aFragWord) * 4;
    const int bFragRow = (lane & 7) + ((lane >> 4) << 3);
    const int bFragWord = ((lane >> 3) & 1) * 4;
    const uint32_t ldB0 = ((wn * 32 + bFragRow) * RSTR + bFragWord) * 4;

    const int nSteps = (CK + 15) >> 4;

    uint32_t pbw[2][4];
    #pragma unroll
    for (int set = 0; set < 2; set++) {
        int k0 = set * 16;
        #pragma unroll
        for (int p = 0; p < 4; p++) {
            int kkg = k0 + bG * 4 + p;
            uint32_t v = 0;
            if (nValid && kkg < CK && set < nSteps) {
                int c = kkg / KW;
                int kw = kkg - c * KW;
                v = Xbase[c * Tin + kw * DIL];
            }
            pbw[set][p] = v;
        }
    }

    cp_async16(baseAH + stA, ArowH);
    cp_async16(baseAL + stA, ArowL);
    CP_COMMIT();
    if (1 < nSteps) {
        cp_async16(baseAH + ASTG_B + stA, ArowH + 16);
        cp_async16(baseAL + ASTG_B + stA, ArowL + 16);
    }
    CP_COMMIT();

    {
        uint32_t h0 = __byte_perm(pbw[0][0], pbw[0][1], 0x5410);
        uint32_t h1 = __byte_perm(pbw[0][2], pbw[0][3], 0x5410);
        uint32_t l0 = __byte_perm(pbw[0][0], pbw[0][1], 0x7632);
        uint32_t l1 = __byte_perm(pbw[0][2], pbw[0][3], 0x7632);
        sts_v2(baseBH + stB, h0, h1);
        sts_v2(baseBL + stB, l0, l1);
    }
    CP_WAIT1();
    __syncthreads();

    for (int s = 0; s < nSteps; s++) {
        if (s + 2 < nSteps) {
            int k0 = (s + 2) * 16;
            #pragma unroll
            for (int p = 0; p < 4; p++) {
                int kkg = k0 + bG * 4 + p;
                uint32_t v = 0;
                if (nValid && kkg < CK) {
                    int c = kkg / KW;
                    int kw = kkg - c * KW;
                    v = Xbase[c * Tin + kw * DIL];
                }
                pbw[s & 1][p] = v;
            }
        }

        if (s + 1 < nSteps) {
            const uint32_t* pw = pbw[(s + 1) & 1];
            const uint32_t offB = ((s + 1) & 1) * BSTG_B;
            uint32_t h0 = __byte_perm(pw[0], pw[1], 0x5410);
            uint32_t h1 = __byte_perm(pw[2], pw[3], 0x5410);
            uint32_t l0 = __byte_perm(pw[0], pw[1], 0x7632);
            uint32_t l1 = __byte_perm(pw[2], pw[3], 0x7632);
            sts_v2(baseBH + offB + stB, h0, h1);
            sts_v2(baseBL + offB + stB, l0, l1);
        }

        if (s + 2 < nSteps) {
            int k0 = (s + 2) * 16;
            const uint32_t offA = ((s + 2) % 3) * ASTG_B;
            cp_async16(baseAH + offA + stA, ArowH + k0);
            cp_async16(baseAL + offA + stA, ArowL + k0);
        }
        CP_COMMIT();

        {
            const uint32_t offA = (s % 3) * ASTG_B;
            const uint32_t offB = (s & 1) * BSTG_B;
            uint32_t bHf[8], bLf[8];
            ldsm_x4(bHf,     baseBH + offB + ldB0);
            ldsm_x4(bHf + 4, baseBH + offB + ldB0 + 16 * RSTR * 4);
            ldsm_x4(bLf,     baseBL + offB + ldB0);
            ldsm_x4(bLf + 4, baseBL + offB + ldB0 + 16 * RSTR * 4);
            #pragma unroll
            for (int mt = 0; mt < 2; mt++) {
                const uint32_t mtOff = mt * 16 * RSTR * 4;
                uint32_t aHf[4], aLf[4];
                ldsm_x4(aHf, baseAH + offA + ldA0 + mtOff);
                ldsm_x4(aLf, baseAL + offA + ldA0 + mtOff);
                #pragma unroll
                for (int nt = 0; nt < 4; nt++) {
                    mma_f16_k16(acc[mt][nt], aHf, bLf + nt * 2);
                    mma_f16_k16(acc[mt][nt], aLf, bHf + nt * 2);
                    mma_f16_k16(acc[mt][nt], aHf, bHf + nt * 2);
                }
            }
        }

        CP_WAIT1();
        __syncthreads();
    }

    // epilogue
    #pragma unroll
    for (int mt = 0; mt < 2; mt++) {
        int row0 = oBase + wm * 32 + mt * 16 + (lane >> 2);
        float b0 = bias[row0];
        float b1 = bias[row0 + 8];
        float s0 = 0.f, q0 = 0.f, s1 = 0.f, q1 = 0.f;
        #pragma unroll
        for (int nt = 0; nt < 4; nt++) {
            int col0 = nBase + wn * 32 + nt * 8 + (lane & 3) * 2;
            #pragma unroll
            for (int cc = 0; cc < 2; cc++) {
                int col = col0 + cc;
                if (col < Ntot) {
                    float v0 = acc[mt][nt][cc]     + b0;
                    float v1 = acc[mt][nt][2 + cc] + b1;
                    int b = col / Tout;
                    int t = col - b * Tout;
                    size_t base = ((size_t)b * Hc) * Tout + t;
                    if (PACK) {
                        Y[base + (size_t)row0 * Tout]       = __uint_as_float(f16_split_pack(v0));
                        Y[base + (size_t)(row0 + 8) * Tout] = __uint_as_float(f16_split_pack(v1));
                    } else {
                        Y[base + (size_t)row0 * Tout]       = v0;
                        Y[base + (size_t)(row0 + 8) * Tout] = v1;
                    }
                    if (STATS) {
                        s0 += v0; q0 += v0 * v0;
                        s1 += v1; q1 += v1 * v1;
                    }
                }
            }
        }
        if (STATS) {
            #pragma unroll
            for (int off = 2; off >= 1; off >>= 1) {
                s0 += __shfl_down_sync(0xffffffffu, s0, off);
                q0 += __shfl_down_sync(0xffffffffu, q0, off);
                s1 += __shfl_down_sync(0xffffffffu, s1, off);
                q1 += __shfl_down_sync(0xffffffffu, q1, off);
            }
            if ((lane & 3) == 0) {
                atomicAdd(&oSum[row0], s0);
                atomicAdd(&oSumsq[row0], q0);
                atomicAdd(&oSum[row0 + 8], s1);
                atomicAdd(&oSumsq[row0 + 8], q1);
            }
        }
    }
}

// ---------------- bottleneck (tensor-core, fp16x3) ----------------
__global__ __launch_bounds__(256)
void bottleneck_tc(const float* __restrict__ W)
{
    const int lane = threadIdx.x & 31;
    const int warp = threadIdx.x >> 5;
    const int o0 = blockIdx.x * 64 + warp * 8;
    const int kb = blockIdx.y * 4096;

    const int r  = lane >> 2;
    const int kq = (lane & 3) * 2;

    const uint32_t* m0 = g_M + (size_t)r * Kbot + kb + kq;
    const uint32_t* m1 = g_M + (size_t)(r + 8) * Kbot + kb + kq;
    const float*    w0 = W + (size_t)(o0 + r) * Kbot + kb + kq;

    float acc[4] = {0.f, 0.f, 0.f, 0.f};

    #pragma unroll 2
    for (int s = 0; s < 4096; s += 16) {
        uint2 u0 = *(const uint2*)(m0 + s);
        uint2 u2 = *(const uint2*)(m0 + s + 8);
        uint2 u1 = *(const uint2*)(m1 + s);
        uint2 u3 = *(const uint2*)(m1 + s + 8);
        float2 wv0 = *(const float2*)(w0 + s);
        float2 wv1 = *(const float2*)(w0 + s + 8);

        uint32_t aH[4], aL[4];
        aH[0] = __byte_perm(u0.x, u0.y, 0x5410);  aL[0] = __byte_perm(u0.x, u0.y, 0x7632);
        aH[1] = __byte_perm(u1.x, u1.y, 0x5410);  aL[1] = __byte_perm(u1.x, u1.y, 0x7632);
        aH[2] = __byte_perm(u2.x, u2.y, 0x5410);  aL[2] = __byte_perm(u2.x, u2.y, 0x7632);
        aH[3] = __byte_perm(u3.x, u3.y, 0x5410);  aL[3] = __byte_perm(u3.x, u3.y, 0x7632);

        uint32_t bH[2], bL[2];
        f16_split2(wv0.x, wv0.y, bH[0], bL[0]);
        f16_split2(wv1.x, wv1.y, bH[1], bL[1]);

        mma_f16_k16(acc, aH, bL);
        mma_f16_k16(acc, aL, bH);
        mma_f16_k16(acc, aH, bH);
    }

    int o = o0 + kq;
    atomicAdd(&g_h[r * Hc + o],           acc[0]);
    atomicAdd(&g_h[r * Hc + o + 1],       acc[1]);
    atomicAdd(&g_h[(r + 8) * Hc + o],     acc[2]);
    atomicAdd(&g_h[(r + 8) * Hc + o + 1], acc[3]);
}

// ---------------- fused bn2d + embedding + L2-norm ----------------
__global__ __launch_bounds__(512)
void emb_fused(const float* __restrict__ bot_b,
               const float* __restrict__ gg, const float* __restrict__ gb,
               const float* __restrict__ Wemb, const float* __restrict__ bemb,
               float* __restrict__ out)
{
    __shared__ float hs[Hc];
    __shared__ float es[Hc];
    __shared__ float red[Hc];

    const int b = blockIdx.x;
    const int o = threadIdx.x;
    const int warp = o >> 5, lane = o & 31;

    {
        float bb = bot_b[o];
        float s = 0.f, q = 0.f, vb = 0.f;
        #pragma unroll
        for (int i = 0; i < Bz; i++) {
            float x = g_h[i * Hc + o] + bb;
            s += x; q += x * x;
            if (i == b) vb = x;
        }
        float m = s * (1.f / 16.f);
        float var = q * (1.f / 16.f) - m * m;
        float a = gg[o] * rsqrtf(var + 1e-5f);
        float d = gb[o] - a * m;
        hs[o] = relu20(a * vb + d);
    }
    __syncthreads();

    for (int e = warp; e < Hc; e += 16) {
        float s = 0.f;
        for (int c = lane; c < Hc; c += 32)
            s += hs[c] * Wemb[e * Hc + c];
        #pragma unroll
        for (int off = 16; off; off >>= 1)
            s += __shfl_down_sync(0xffffffffu, s, off);
        if (lane == 0) es[e] = s + bemb[e];
    }
    __syncthreads();

    float v = es[o];
    red[o] = v * v;
    __syncthreads();
    for (int st = 256; st > 0; st >>= 1) {
        if (o < st) red[o] += red[o + st];
        __syncthreads();
    }
    float scale = 10.f / sqrtf(red[0] + 1e-10f);
    out[b * Hc + o] = v * scale;
}

// ---------------- launcher ----------------
extern "C" void kernel_launch(void* const* d_in, const int* in_sizes, int n_in,
                              void* d_out, int out_size)
{
    const float* input_x = (const float*)d_in[0];
    const float* conv1_b = (const float*)d_in[2];
    const float* bn1_g   = (const float*)d_in[3];
    const float* bn1_b   = (const float*)d_in[4];
    const float* conv2_b = (const float*)d_in[6];
    const float* bn2_g   = (const float*)d_in[7];
    const float* bn2_b   = (const float*)d_in[8];
    const float* conv3_b = (const float*)d_in[10];
    const float* bn3_g   = (const float*)d_in[11];
    const float* bn3_b   = (const float*)d_in[12];
    const float* lin4_b  = (const float*)d_in[14];
    const float* bn4_g   = (const float*)d_in[15];
    const float* bn4_b   = (const float*)d_in[16];
    const float* lin5_b  = (const float*)d_in[18];
    const float* bn5_g   = (const float*)d_in[19];
    const float* bn5_b   = (const float*)d_in[20];
    const float* bot_w   = (const float*)d_in[21];
    const float* bot_b   = (const float*)d_in[22];
    const float* bnb_g   = (const float*)d_in[23];
    const float* bnb_b   = (const float*)d_in[24];
    const float* emb_w   = (const float*)d_in[25];
    const float* emb_b   = (const float*)d_in[26];
    float* out = (float*)d_out;

    float *pA, *p2, *pZero, *pSums, *pSumsqs;
    uint32_t *pAct, *pMf;
    __half *pWH, *pWL, *pX5H, *pX5L;
    cudaGetSymbolAddress((void**)&pA,     g_bufA);
    cudaGetSymbolAddress((void**)&p2,     g_buf2);
    cudaGetSymbolAddress((void**)&pAct,   g_act);
    cudaGetSymbolAddress((void**)&pWH,    g_wH);
    cudaGetSymbolAddress((void**)&pWL,    g_wL);
    cudaGetSymbolAddress((void**)&pX5H,   g_x5H);
    cudaGetSymbolAddress((void**)&pX5L,   g_x5L);
    cudaGetSymbolAddress((void**)&pMf,    g_M);
    cudaGetSymbolAddress((void**)&pZero,  g_zero);
    cudaGetSymbolAddress((void**)&pSums,  g_sums);
    cudaGetSymbolAddress((void**)&pSumsqs,g_sumsqs);

    prep<<<(WTOT + 255) / 256, 256>>>(input_x,
        (const float*)d_in[1], (const float*)d_in[5], (const float*)d_in[9],
        (const float*)d_in[13], (const float*)d_in[17]);

    // conv1: CK=200, T 400->396, N=6336 -> bufA  (bias+stats in GEMM)
    conv_gemm<5,1,true,false><<<dim3(99, 4, 1), 256>>>(
        pWH + WO1, pWL + WO1, conv1_b, pAct, pA,
        pSums + 0*Hc, pSumsqs + 0*Hc,
        40, 400, 396, 200, 200, 6336, 0, 0, 0);
    split_bn<false><<<148, 512>>>(pA, pAct, nullptr, nullptr,
                                  pSums + 0*Hc, pSumsqs + 0*Hc, bn1_g, bn1_b,
                                  1.f / 6336.f, 396, Bz * Hc * 396);

    // conv2 split-K: CK half = 768, ldA = 1536; z selects half. No bias/stats in GEMM.
    conv_gemm<3,2,false,false><<<dim3(98, 4, 2), 256>>>(
        pWH + WO2, pWL + WO2, pZero, pAct, p2,
        nullptr, nullptr,
        512, 396, 392, 768, 1536, 6272,
        768 /*A col offset*/, 256 * 396 /*X offset*/, OFF2 /*Y half*/);
    stats2<<<512, 256>>>(p2, p2 + OFF2, conv2_b, pSums + 1*Hc, pSumsqs + 1*Hc, 392);
    split_bn2<<<148, 512>>>(p2, p2 + OFF2, conv2_b, pAct,
                            pSums + 1*Hc, pSumsqs + 1*Hc, bn2_g, bn2_b,
                            1.f / 6272.f, 392, Bz * Hc * 392);

    // conv3 split-K: same scheme, dil=4, Tin=392
    conv_gemm<3,4,false,false><<<dim3(96, 4, 2), 256>>>(
        pWH + WO3, pWL + WO3, pZero, pAct, p2,
        nullptr, nullptr,
        512, 392, 384, 768, 1536, 6144,
        768, 256 * 392, OFF2);
    stats2<<<512, 256>>>(p2, p2 + OFF2, conv3_b, pSums + 2*Hc, pSumsqs + 2*Hc, 384);
    split_bn2<<<148, 512>>>(p2, p2 + OFF2, conv3_b, pAct,
                            pSums + 2*Hc, pSumsqs + 2*Hc, bn3_g, bn3_b,
                            1.f / 6144.f, 384, Bz * Hc * 384);

    // lin4: CK=512 -> bufA (bias+stats in GEMM)
    conv_gemm<1,1,true,false><<<dim3(96, 4, 1), 256>>>(
        pWH + WO4, pWL + WO4, lin4_b, pAct, pA,
        pSums + 3*Hc, pSumsqs + 3*Hc,
        512, 384, 384, 512, 512, 6144, 0, 0, 0);
    split_bn<false><<<148, 512>>>(pA, pAct, nullptr, nullptr,
                                  pSums + 3*Hc, pSumsqs + 3*Hc, bn4_g, bn4_b,
                                  1.f / 6144.f, 384, Bz * Hc * 384);   // x4 packed

    // lin5: reads x4 packed -> raw x5 (into buf2 low half)
    conv_gemm<1,1,true,false><<<dim3(96, 4, 1), 256>>>(
        pWH + WO5, pWL + WO5, lin5_b, pAct, p2,
        pSums + 4*Hc, pSumsqs + 4*Hc,
        512, 384, 384, 512, 512, 6144, 0, 0, 0);
    split_bn<true><<<148, 512>>>(p2, nullptr, pX5H, pX5L,
                                 pSums + 4*Hc, pSumsqs + 4*Hc, bn5_g, bn5_b,
                                 1.f / 6144.f, 384, Bz * Hc * 384);    // x5 planes

    // pooling: A = x5 planes, X = x4 packed; PACK -> g_M
    conv_gemm<1,1,false,true><<<dim3(8, 4, 16), 256>>>(
        pX5H, pX5L, pZero, pAct, (float*)pMf,
        nullptr, nullptr,
        384, 1, 1, 384, 384, 512, Hc * T3c, Hc * T3c, Kbot);

    // bottleneck: tensor-core fp16x3 (g_h zeroed by prep)
    bottleneck_tc<<<dim3(8, 64), 256>>>(bot_w);

    // fused bn2d + embedding + norm
    emb_fused<<<16, 512>>>(bot_b, bnb_g, bnb_b, emb_w, emb_b, out);
}

// round 16
// speedup vs baseline: 1.0128x; 1.0128x over previous
#include <cuda_runtime.h>
#include <cuda_fp16.h>
#include <math.h>
#include <stdint.h>

// ---------------- problem constants ----------------
#define Bz   16
#define T0   400
#define F0c  40
#define Hc   512
#define T1c  396
#define T3c  384
#define Kbot (Hc*Hc)   // 262144

// weight arena offsets (elements)
#define WO1 0
#define WO2 102400
#define WO3 888832
#define WO4 1675264
#define WO5 1937408
#define WTOT 2199552

// ---------------- scratch ----------------
__device__ float g_bufA[Bz*Hc*T1c];          // raw fp32 GEMM outputs
__device__ uint32_t g_act[Bz*Hc*T1c];        // packed (lo16|hi16) split activations
__device__ __half g_wH[WTOT];
__device__ __half g_wL[WTOT];
__device__ uint32_t g_M[Bz*Kbot];            // pooled matrices, packed
__device__ float g_sums[5][Hc];
__device__ float g_sumsqs[5][Hc];
__device__ float g_h[Bz*Hc];
__device__ float g_zero[Hc];

// ---------------- helpers ----------------
__device__ __forceinline__ float relu20(float v)
{
    return fminf(fmaxf(v, 0.f), 20.f);
}

__device__ __forceinline__ uint32_t f16_split_pack(float v)
{
    __half h = __float2half_rn(v);
    __half l = __float2half_rn(v - __half2float(h));
    return ((uint32_t)__half_as_ushort(l) << 16) | (uint32_t)__half_as_ushort(h);
}

__device__ __forceinline__ void f16_split2(float x0, float x1, uint32_t& hw, uint32_t& lw)
{
    __half2 h = __floats2half2_rn(x0, x1);
    float2 hf = __half22float2(h);
    __half2 l = __floats2half2_rn(x0 - hf.x, x1 - hf.y);
    hw = *(uint32_t*)&h;
    lw = *(uint32_t*)&l;
}

__device__ __forceinline__ void mma_f16_k16(float* d, const uint32_t* a, const uint32_t* b)
{
    asm volatile(
        "mma.sync.aligned.m16n8k16.row.col.f32.f16.f16.f32 "
        "{%0,%1,%2,%3}, {%4,%5,%6,%7}, {%8,%9}, {%0,%1,%2,%3};"
        : "+f"(d[0]), "+f"(d[1]), "+f"(d[2]), "+f"(d[3])
        : "r"(a[0]), "r"(a[1]), "r"(a[2]), "r"(a[3]), "r"(b[0]), "r"(b[1]));
}

__device__ __forceinline__ void ldsm_x4(uint32_t* r, uint32_t saddr)
{
    asm volatile("ldmatrix.sync.aligned.m8n8.x4.shared.b16 {%0,%1,%2,%3}, [%4];"
        : "=r"(r[0]), "=r"(r[1]), "=r"(r[2]), "=r"(r[3]) : "r"(saddr));
}

__device__ __forceinline__ void sts_v2(uint32_t saddr, uint32_t v0, uint32_t v1)
{
    asm volatile("st.shared.v2.u32 [%0], {%1,%2};" :: "r"(saddr), "r"(v0), "r"(v1));
}

__device__ __forceinline__ void sts_v4(uint32_t saddr, uint32_t v0, uint32_t v1,
                                       uint32_t v2, uint32_t v3)
{
    asm volatile("st.shared.v4.u32 [%0], {%1,%2,%3,%4};"
        :: "r"(saddr), "r"(v0), "r"(v1), "r"(v2), "r"(v3));
}

__device__ __forceinline__ void cp_async16(uint32_t saddr, const void* gaddr)
{
    asm volatile("cp.async.cg.shared.global [%0], [%1], 16;"
        :: "r"(saddr), "l"(gaddr));
}
#define CP_COMMIT() asm volatile("cp.async.commit_group;")
#define CP_WAIT1()  asm volatile("cp.async.wait_group 1;")

// ---------------- prep ----------------
__global__ void prep(const float* __restrict__ in,
                     const float* __restrict__ w1, const float* __restrict__ w2,
                     const float* __restrict__ w3, const float* __restrict__ w4,
                     const float* __restrict__ w5)
{
    int i = blockIdx.x * blockDim.x + threadIdx.x;
    if (i < WTOT) {
        float v;
        if (i < WO2)      v = w1[i];
        else if (i < WO3) v = w2[i - WO2];
        else if (i < WO4) v = w3[i - WO3];
        else if (i < WO5) v = w4[i - WO4];
        else              v = w5[i - WO5];
        __half h = __float2half_rn(v);
        g_wH[i] = h;
        g_wL[i] = __float2half_rn(v - __half2float(h));
    }
    if (i < Bz * T0 * F0c) {
        int c = i % F0c;
        int t = (i / F0c) % T0;
        int b = i / (F0c * T0);
        g_act[(b * F0c + c) * T0 + t] = f16_split_pack(in[i]);
    }
    if (i < 5 * Hc) {
        (&g_sums[0][0])[i] = 0.f;
        (&g_sumsqs[0][0])[i] = 0.f;
    }
    if (i < Bz * Hc) {
        g_h[i] = 0.f;
    }
}

// ---------------- BN finalize+apply+clamp+split -> packed ----------------
__global__ __launch_bounds__(512)
void split_bn(const float* __restrict__ Y, uint32_t* __restrict__ dst,
              const float* __restrict__ sums, const float* __restrict__ sumsqs,
              const float* __restrict__ gamma, const float* __restrict__ beta,
              float invN, int T, int total)
{
    __shared__ float sSc[Hc];
    __shared__ float sSh[Hc];
    {
        int c = threadIdx.x;
        float s = sums[c], q = sumsqs[c];
        float m = s * invN;
        float var = q * invN - m * m;
        float a = gamma[c] * rsqrtf(var + 1e-5f);
        sSc[c] = a;
        sSh[c] = beta[c] - a * m;
    }
    __syncthreads();
    for (int idx = blockIdx.x * 512 + threadIdx.x; idx < total; idx += gridDim.x * 512) {
        int c = (idx / T) & (Hc - 1);
        float v = relu20(sSc[c] * Y[idx] + sSh[c]);
        __half h = __float2half_rn(v);
        __half l = __float2half_rn(v - __half2float(h));
        dst[idx] = ((uint32_t)__half_as_ushort(l) << 16) | (uint32_t)__half_as_ushort(h);
    }
}

// ---------------- FP16x3 conv-as-GEMM ----------------
// MODEA 0: A = pre-split fp16 hi/lo planes, cp.async 3-stage.
// MODEA 1: A = raw fp32 rows + per-row BN(iSum/iSumsq/gA/bA) + clamp + split,
//          register-prefetched at distance 2 and staged via STS (pooling).
// B: packed (lo16|hi16) uint32 activations, im2col gather at distance 2.
// STATS: per-row sum/sumsq of (acc+bias). PACK: packed split output (-> g_M).
#define RSTR 12
#define ASTG_B (128 * RSTR * 4)
#define BSTG_B (64 * RSTR * 4)
template<int KW, int DIL, int MODEA, bool STATS, bool PACK, int MINB>
__global__ __launch_bounds__(256, MINB)
void conv_gemm(const __half* __restrict__ AH, const __half* __restrict__ AL,
               const float* __restrict__ Araw,
               const float* __restrict__ iSum, const float* __restrict__ iSumsq,
               const float* __restrict__ gA, const float* __restrict__ bA, float invN,
               const float* __restrict__ bias,
               const uint32_t* __restrict__ X, float* __restrict__ Y,
               float* __restrict__ oSum, float* __restrict__ oSumsq,
               int C, int Tin, int Tout, int CK, int ldA, int Ntot,
               int strideA, int strideX, int strideY)
{
    X += (size_t)blockIdx.z * strideX;
    Y += (size_t)blockIdx.z * strideY;

    __shared__ uint32_t AsH[3][128][RSTR];
    __shared__ uint32_t AsL[3][128][RSTR];
    __shared__ uint32_t BsH[2][64][RSTR];
    __shared__ uint32_t BsL[2][64][RSTR];

    const int tid  = threadIdx.x;
    const int lane = tid & 31;
    const int warp = tid >> 5;
    const int wm = warp >> 1;
    const int wn = warp & 1;
    const int oBase = blockIdx.y * 128;
    const int nBase = blockIdx.x * 64;

    float acc[2][4][4];
    #pragma unroll
    for (int i = 0; i < 2; i++)
        #pragma unroll
        for (int j = 0; j < 4; j++)
            #pragma unroll
            for (int r = 0; r < 4; r++) acc[i][j][r] = 0.f;

    const int aRow = tid >> 1;
    const int bN  = tid & 63;
    const int bG  = tid >> 6;

    const int nIdx = nBase + bN;
    const bool nValid = (nIdx < Ntot);
    int nb = 0, nt0 = 0;
    if (nValid) { nb = nIdx / Tout; nt0 = nIdx - nb * Tout; }
    const uint32_t* Xbase = X + ((size_t)nb * C) * Tin + nt0;

    const __half* ArowH = AH + (size_t)blockIdx.z * strideA
                          + (size_t)(oBase + aRow) * ldA + (tid & 1) * 8;
    const __half* ArowL = AL + (size_t)blockIdx.z * strideA
                          + (size_t)(oBase + aRow) * ldA + (tid & 1) * 8;
    const float* ArawRow = (MODEA == 1)
        ? Araw + (size_t)blockIdx.z * strideA + (size_t)(oBase + aRow) * ldA + (tid & 1) * 8
        : nullptr;

    // MODEA 1: per-row BN constants (row channel = oBase + aRow)
    float aSc = 1.f, aSh = 0.f;
    if (MODEA == 1) {
        int ch = oBase + aRow;
        float s = iSum[ch], q = iSumsq[ch];
        float m = s * invN;
        float var = q * invN - m * m;
        aSc = gA[ch] * rsqrtf(var + 1e-5f);
        aSh = bA[ch] - aSc * m;
    }

    const uint32_t baseAH = (uint32_t)__cvta_generic_to_shared(&AsH[0][0][0]);
    const uint32_t baseAL = (uint32_t)__cvta_generic_to_shared(&AsL[0][0][0]);
    const uint32_t baseBH = (uint32_t)__cvta_generic_to_shared(&BsH[0][0][0]);
    const uint32_t baseBL = (uint32_t)__cvta_generic_to_shared(&BsL[0][0][0]);

    const uint32_t stA = (aRow * RSTR + (tid & 1) * 4) * 4;
    const uint32_t stB = (bN * RSTR + bG * 2) * 4;

    const int aFragRow = (lane & 7) + ((lane >> 3) & 1) * 8;
    const int aFragWord = (lane >> 4) * 4;
    const uint32_t ldA0 = ((wm * 32 + aFragRow) * RSTR + aFragWord) * 4;
    const int bFragRow = (lane & 7) + ((lane >> 4) << 3);
    const int bFragWord = ((lane >> 3) & 1) * 4;
    const uint32_t ldB0 = ((wn * 32 + bFragRow) * RSTR + bFragWord) * 4;

    const int nSteps = (CK + 15) >> 4;

    // B register prefetch (distance 2)
    uint32_t pbw[2][4];
    #pragma unroll
    for (int set = 0; set < 2; set++) {
        int k0 = set * 16;
        #pragma unroll
        for (int p = 0; p < 4; p++) {
            int kkg = k0 + bG * 4 + p;
            uint32_t v = 0;
            if (nValid && kkg < CK && set < nSteps) {
                int c = kkg / KW;
                int kw = kkg - c * KW;
                v = Xbase[c * Tin + kw * DIL];
            }
            pbw[set][p] = v;
        }
    }

    // A register prefetch for MODEA 1 (distance 2, BN applied)
    float paw[2][8];
    if (MODEA == 1) {
        #pragma unroll
        for (int set = 0; set < 2; set++) {
            int k0 = set * 16;
            if (set < nSteps) {
                float4 a0 = *(const float4*)(ArawRow + k0);
                float4 a1 = *(const float4*)(ArawRow + k0 + 4);
                paw[set][0] = relu20(aSc * a0.x + aSh);
                paw[set][1] = relu20(aSc * a0.y + aSh);
                paw[set][2] = relu20(aSc * a0.z + aSh);
                paw[set][3] = relu20(aSc * a0.w + aSh);
                paw[set][4] = relu20(aSc * a1.x + aSh);
                paw[set][5] = relu20(aSc * a1.y + aSh);
                paw[set][6] = relu20(aSc * a1.z + aSh);
                paw[set][7] = relu20(aSc * a1.w + aSh);
            }
        }
    }

    if (MODEA == 0) {
        cp_async16(baseAH + stA, ArowH);
        cp_async16(baseAL + stA, ArowL);
        CP_COMMIT();
        if (1 < nSteps) {
            cp_async16(baseAH + ASTG_B + stA, ArowH + 16);
            cp_async16(baseAL + ASTG_B + stA, ArowL + 16);
        }
        CP_COMMIT();
    } else {
        // stage A[0] from registers
        uint32_t h0, l0, h1, l1, h2, l2, h3, l3;
        f16_split2(paw[0][0], paw[0][1], h0, l0);
        f16_split2(paw[0][2], paw[0][3], h1, l1);
        f16_split2(paw[0][4], paw[0][5], h2, l2);
        f16_split2(paw[0][6], paw[0][7], h3, l3);
        sts_v4(baseAH + stA, h0, h1, h2, h3);
        sts_v4(baseAL + stA, l0, l1, l2, l3);
    }

    // stage B[0]
    {
        uint32_t h0 = __byte_perm(pbw[0][0], pbw[0][1], 0x5410);
        uint32_t h1 = __byte_perm(pbw[0][2], pbw[0][3], 0x5410);
        uint32_t l0 = __byte_perm(pbw[0][0], pbw[0][1], 0x7632);
        uint32_t l1 = __byte_perm(pbw[0][2], pbw[0][3], 0x7632);
        sts_v2(baseBH + stB, h0, h1);
        sts_v2(baseBL + stB, l0, l1);
    }
    if (MODEA == 0) { CP_WAIT1(); }
    __syncthreads();

    for (int s = 0; s < nSteps; s++) {
        // LDG B[s+2]
        if (s + 2 < nSteps) {
            int k0 = (s + 2) * 16;
            #pragma unroll
            for (int p = 0; p < 4; p++) {
                int kkg = k0 + bG * 4 + p;
                uint32_t v = 0;
                if (nValid && kkg < CK) {
                    int c = kkg / KW;
                    int kw = kkg - c * KW;
                    v = Xbase[c * Tin + kw * DIL];
                }
                pbw[s & 1][p] = v;
            }
        }
        // LDG A[s+2] (MODEA 1)
        if (MODEA == 1 && s + 2 < nSteps) {
            int k0 = (s + 2) * 16;
            float4 a0 = *(const float4*)(ArawRow + k0);
            float4 a1 = *(const float4*)(ArawRow + k0 + 4);
            paw[s & 1][0] = relu20(aSc * a0.x + aSh);
            paw[s & 1][1] = relu20(aSc * a0.y + aSh);
            paw[s & 1][2] = relu20(aSc * a0.z + aSh);
            paw[s & 1][3] = relu20(aSc * a0.w + aSh);
            paw[s & 1][4] = relu20(aSc * a1.x + aSh);
            paw[s & 1][5] = relu20(aSc * a1.y + aSh);
            paw[s & 1][6] = relu20(aSc * a1.z + aSh);
            paw[s & 1][7] = relu20(aSc * a1.w + aSh);
        }

        // STS B[s+1]
        if (s + 1 < nSteps) {
            const uint32_t* pw = pbw[(s + 1) & 1];
            const uint32_t offB = ((s + 1) & 1) * BSTG_B;
            uint32_t h0 = __byte_perm(pw[0], pw[1], 0x5410);
            uint32_t h1 = __byte_perm(pw[2], pw[3], 0x5410);
            uint32_t l0 = __byte_perm(pw[0], pw[1], 0x7632);
            uint32_t l1 = __byte_perm(pw[2], pw[3], 0x7632);
            sts_v2(baseBH + offB + stB, h0, h1);
            sts_v2(baseBL + offB + stB, l0, l1);
        }
        // STS A[s+1] (MODEA 1)
        if (MODEA == 1 && s + 1 < nSteps) {
            const float* pw = paw[(s + 1) & 1];
            const uint32_t offA = ((s + 1) % 3) * ASTG_B;
            uint32_t h0, l0, h1, l1, h2, l2, h3, l3;
            f16_split2(pw[0], pw[1], h0, l0);
            f16_split2(pw[2], pw[3], h1, l1);
            f16_split2(pw[4], pw[5], h2, l2);
            f16_split2(pw[6], pw[7], h3, l3);
            sts_v4(baseAH + offA + stA, h0, h1, h2, h3);
            sts_v4(baseAL + offA + stA, l0, l1, l2, l3);
        }

        // cp.async A[s+2] (MODEA 0)
        if (MODEA == 0) {
            if (s + 2 < nSteps) {
                int k0 = (s + 2) * 16;
                const uint32_t offA = ((s + 2) % 3) * ASTG_B;
                cp_async16(baseAH + offA + stA, ArowH + k0);
                cp_async16(baseAL + offA + stA, ArowL + k0);
            }
            CP_COMMIT();
        }

        // consume step s
        {
            const uint32_t offA = (s % 3) * ASTG_B;
            const uint32_t offB = (s & 1) * BSTG_B;
            uint32_t bHf[8], bLf[8];
            ldsm_x4(bHf,     baseBH + offB + ldB0);
            ldsm_x4(bHf + 4, baseBH + offB + ldB0 + 16 * RSTR * 4);
            ldsm_x4(bLf,     baseBL + offB + ldB0);
            ldsm_x4(bLf + 4, baseBL + offB + ldB0 + 16 * RSTR * 4);
            #pragma unroll
            for (int mt = 0; mt < 2; mt++) {
                const uint32_t mtOff = mt * 16 * RSTR * 4;
                uint32_t aHf[4], aLf[4];
                ldsm_x4(aHf, baseAH + offA + ldA0 + mtOff);
                ldsm_x4(aLf, baseAL + offA + ldA0 + mtOff);
                #pragma unroll
                for (int nt = 0; nt < 4; nt++) {
                    mma_f16_k16(acc[mt][nt], aHf, bLf + nt * 2);
                    mma_f16_k16(acc[mt][nt], aLf, bHf + nt * 2);
                    mma_f16_k16(acc[mt][nt], aHf, bHf + nt * 2);
                }
            }
        }

        if (MODEA == 0) { CP_WAIT1(); }
        __syncthreads();
    }

    // epilogue
    #pragma unroll
    for (int mt = 0; mt < 2; mt++) {
        int row0 = oBase + wm * 32 + mt * 16 + (lane >> 2);
        float b0 = bias[row0];
        float b1 = bias[row0 + 8];
        float s0 = 0.f, q0 = 0.f, s1 = 0.f, q1 = 0.f;
        #pragma unroll
        for (int nt = 0; nt < 4; nt++) {
            int col0 = nBase + wn * 32 + nt * 8 + (lane & 3) * 2;
            #pragma unroll
            for (int cc = 0; cc < 2; cc++) {
                int col = col0 + cc;
                if (col < Ntot) {
                    float v0 = acc[mt][nt][cc]     + b0;
                    float v1 = acc[mt][nt][2 + cc] + b1;
                    int b = col / Tout;
                    int t = col - b * Tout;
                    size_t base = ((size_t)b * Hc) * Tout + t;
                    if (PACK) {
                        Y[base + (size_t)row0 * Tout]       = __uint_as_float(f16_split_pack(v0));
                        Y[base + (size_t)(row0 + 8) * Tout] = __uint_as_float(f16_split_pack(v1));
                    } else {
                        Y[base + (size_t)row0 * Tout]       = v0;
                        Y[base + (size_t)(row0 + 8) * Tout] = v1;
                    }
                    if (STATS) {
                        s0 += v0; q0 += v0 * v0;
                        s1 += v1; q1 += v1 * v1;
                    }
                }
            }
        }
        if (STATS) {
            #pragma unroll
            for (int off = 2; off >= 1; off >>= 1) {
                s0 += __shfl_down_sync(0xffffffffu, s0, off);
                q0 += __shfl_down_sync(0xffffffffu, q0, off);
                s1 += __shfl_down_sync(0xffffffffu, s1, off);
                q1 += __shfl_down_sync(0xffffffffu, q1, off);
            }
            if ((lane & 3) == 0) {
                atomicAdd(&oSum[row0], s0);
                atomicAdd(&oSumsq[row0], q0);
                atomicAdd(&oSum[row0 + 8], s1);
                atomicAdd(&oSumsq[row0 + 8], q1);
            }
        }
    }
}

// ---------------- bottleneck (tensor-core, fp16x3) ----------------
__global__ __launch_bounds__(256)
void bottleneck_tc(const float* __restrict__ W)
{
    const int lane = threadIdx.x & 31;
    const int warp = threadIdx.x >> 5;
    const int o0 = blockIdx.x * 64 + warp * 8;
    const int kb = blockIdx.y * 4096;

    const int r  = lane >> 2;
    const int kq = (lane & 3) * 2;

    const uint32_t* m0 = g_M + (size_t)r * Kbot + kb + kq;
    const uint32_t* m1 = g_M + (size_t)(r + 8) * Kbot + kb + kq;
    const float*    w0 = W + (size_t)(o0 + r) * Kbot + kb + kq;

    float acc[4] = {0.f, 0.f, 0.f, 0.f};

    #pragma unroll 2
    for (int s = 0; s < 4096; s += 16) {
        uint2 u0 = *(const uint2*)(m0 + s);
        uint2 u2 = *(const uint2*)(m0 + s + 8);
        uint2 u1 = *(const uint2*)(m1 + s);
        uint2 u3 = *(const uint2*)(m1 + s + 8);
        float2 wv0 = *(const float2*)(w0 + s);
        float2 wv1 = *(const float2*)(w0 + s + 8);

        uint32_t aH[4], aL[4];
        aH[0] = __byte_perm(u0.x, u0.y, 0x5410);  aL[0] = __byte_perm(u0.x, u0.y, 0x7632);
        aH[1] = __byte_perm(u1.x, u1.y, 0x5410);  aL[1] = __byte_perm(u1.x, u1.y, 0x7632);
        aH[2] = __byte_perm(u2.x, u2.y, 0x5410);  aL[2] = __byte_perm(u2.x, u2.y, 0x7632);
        aH[3] = __byte_perm(u3.x, u3.y, 0x5410);  aL[3] = __byte_perm(u3.x, u3.y, 0x7632);

        uint32_t bH[2], bL[2];
        f16_split2(wv0.x, wv0.y, bH[0], bL[0]);
        f16_split2(wv1.x, wv1.y, bH[1], bL[1]);

        mma_f16_k16(acc, aH, bL);
        mma_f16_k16(acc, aL, bH);
        mma_f16_k16(acc, aH, bH);
    }

    int o = o0 + kq;
    atomicAdd(&g_h[r * Hc + o],           acc[0]);
    atomicAdd(&g_h[r * Hc + o + 1],       acc[1]);
    atomicAdd(&g_h[(r + 8) * Hc + o],     acc[2]);
    atomicAdd(&g_h[(r + 8) * Hc + o + 1], acc[3]);
}

// ---------------- fused bn2d + embedding + L2-norm ----------------
__global__ __launch_bounds__(512)
void emb_fused(const float* __restrict__ bot_b,
               const float* __restrict__ gg, const float* __restrict__ gb,
               const float* __restrict__ Wemb, const float* __restrict__ bemb,
               float* __restrict__ out)
{
    __shared__ float hs[Hc];
    __shared__ float es[Hc];
    __shared__ float red[Hc];

    const int b = blockIdx.x;
    const int o = threadIdx.x;
    const int warp = o >> 5, lane = o & 31;

    {
        float bb = bot_b[o];
        float s = 0.f, q = 0.f, vb = 0.f;
        #pragma unroll
        for (int i = 0; i < Bz; i++) {
            float x = g_h[i * Hc + o] + bb;
            s += x; q += x * x;
            if (i == b) vb = x;
        }
        float m = s * (1.f / 16.f);
        float var = q * (1.f / 16.f) - m * m;
        float a = gg[o] * rsqrtf(var + 1e-5f);
        float d = gb[o] - a * m;
        hs[o] = relu20(a * vb + d);
    }
    __syncthreads();

    for (int e = warp; e < Hc; e += 16) {
        float s = 0.f;
        for (int c = lane; c < Hc; c += 32)
            s += hs[c] * Wemb[e * Hc + c];
        #pragma unroll
        for (int off = 16; off; off >>= 1)
            s += __shfl_down_sync(0xffffffffu, s, off);
        if (lane == 0) es[e] = s + bemb[e];
    }
    __syncthreads();

    float v = es[o];
    red[o] = v * v;
    __syncthreads();
    for (int st = 256; st > 0; st >>= 1) {
        if (o < st) red[o] += red[o + st];
        __syncthreads();
    }
    float scale = 10.f / sqrtf(red[0] + 1e-10f);
    out[b * Hc + o] = v * scale;
}

// ---------------- launcher ----------------
extern "C" void kernel_launch(void* const* d_in, const int* in_sizes, int n_in,
                              void* d_out, int out_size)
{
    const float* input_x = (const float*)d_in[0];
    const float* conv1_b = (const float*)d_in[2];
    const float* bn1_g   = (const float*)d_in[3];
    const float* bn1_b   = (const float*)d_in[4];
    const float* conv2_b = (const float*)d_in[6];
    const float* bn2_g   = (const float*)d_in[7];
    const float* bn2_b   = (const float*)d_in[8];
    const float* conv3_b = (const float*)d_in[10];
    const float* bn3_g   = (const float*)d_in[11];
    const float* bn3_b   = (const float*)d_in[12];
    const float* lin4_b  = (const float*)d_in[14];
    const float* bn4_g   = (const float*)d_in[15];
    const float* bn4_b   = (const float*)d_in[16];
    const float* lin5_b  = (const float*)d_in[18];
    const float* bn5_g   = (const float*)d_in[19];
    const float* bn5_b   = (const float*)d_in[20];
    const float* bot_w   = (const float*)d_in[21];
    const float* bot_b   = (const float*)d_in[22];
    const float* bnb_g   = (const float*)d_in[23];
    const float* bnb_b   = (const float*)d_in[24];
    const float* emb_w   = (const float*)d_in[25];
    const float* emb_b   = (const float*)d_in[26];
    float* out = (float*)d_out;

    float *pA, *pZero, *pSums, *pSumsqs;
    uint32_t *pAct, *pMf;
    __half *pWH, *pWL;
    cudaGetSymbolAddress((void**)&pA,     g_bufA);
    cudaGetSymbolAddress((void**)&pAct,   g_act);
    cudaGetSymbolAddress((void**)&pWH,    g_wH);
    cudaGetSymbolAddress((void**)&pWL,    g_wL);
    cudaGetSymbolAddress((void**)&pMf,    g_M);
    cudaGetSymbolAddress((void**)&pZero,  g_zero);
    cudaGetSymbolAddress((void**)&pSums,  g_sums);
    cudaGetSymbolAddress((void**)&pSumsqs,g_sumsqs);

    prep<<<(WTOT + 255) / 256, 256>>>(input_x,
        (const float*)d_in[1], (const float*)d_in[5], (const float*)d_in[9],
        (const float*)d_in[13], (const float*)d_in[17]);

    // conv1: CK=200, T 400->396, N=6336 -> bufA
    conv_gemm<5,1,0,true,false,3><<<dim3(99, 4, 1), 256>>>(
        pWH + WO1, pWL + WO1, nullptr, nullptr, nullptr, nullptr, nullptr, 0.f,
        conv1_b, pAct, pA, pSums + 0*Hc, pSumsqs + 0*Hc,
        40, 400, 396, 200, 200, 6336, 0, 0, 0);
    split_bn<<<148, 512>>>(pA, pAct, pSums + 0*Hc, pSumsqs + 0*Hc, bn1_g, bn1_b,
                           1.f / 6336.f, 396, Bz * Hc * 396);

    // conv2: CK=1536, T 396->392, N=6272 -> bufA
    conv_gemm<3,2,0,true,false,3><<<dim3(98, 4, 1), 256>>>(
        pWH + WO2, pWL + WO2, nullptr, nullptr, nullptr, nullptr, nullptr, 0.f,
        conv2_b, pAct, pA, pSums + 1*Hc, pSumsqs + 1*Hc,
        512, 396, 392, 1536, 1536, 6272, 0, 0, 0);
    split_bn<<<148, 512>>>(pA, pAct, pSums + 1*Hc, pSumsqs + 1*Hc, bn2_g, bn2_b,
                           1.f / 6272.f, 392, Bz * Hc * 392);

    // conv3: CK=1536, T 392->384, N=6144 -> bufA
    conv_gemm<3,4,0,true,false,3><<<dim3(96, 4, 1), 256>>>(
        pWH + WO3, pWL + WO3, nullptr, nullptr, nullptr, nullptr, nullptr, 0.f,
        conv3_b, pAct, pA, pSums + 2*Hc, pSumsqs + 2*Hc,
        512, 392, 384, 1536, 1536, 6144, 0, 0, 0);
    split_bn<<<148, 512>>>(pA, pAct, pSums + 2*Hc, pSumsqs + 2*Hc, bn3_g, bn3_b,
                           1.f / 6144.f, 384, Bz * Hc * 384);

    // lin4: CK=512, T=384 -> bufA
    conv_gemm<1,1,0,true,false,3><<<dim3(96, 4, 1), 256>>>(
        pWH + WO4, pWL + WO4, nullptr, nullptr, nullptr, nullptr, nullptr, 0.f,
        lin4_b, pAct, pA, pSums + 3*Hc, pSumsqs + 3*Hc,
        512, 384, 384, 512, 512, 6144, 0, 0, 0);
    split_bn<<<148, 512>>>(pA, pAct, pSums + 3*Hc, pSumsqs + 3*Hc, bn4_g, bn4_b,
                           1.f / 6144.f, 384, Bz * Hc * 384);   // x4 packed

    // lin5: reads x4 packed -> raw x5 in bufA
    conv_gemm<1,1,0,true,false,3><<<dim3(96, 4, 1), 256>>>(
        pWH + WO5, pWL + WO5, nullptr, nullptr, nullptr, nullptr, nullptr, 0.f,
        lin5_b, pAct, pA, pSums + 4*Hc, pSumsqs + 4*Hc,
        512, 384, 384, 512, 512, 6144, 0, 0, 0);

    // pooling: A = raw x5 (bufA) with fused BN5 (MODEA=1), B = x4 packed; PACK -> g_M
    conv_gemm<1,1,1,false,true,2><<<dim3(8, 4, 16), 256>>>(
        nullptr, nullptr, pA, pSums + 4*Hc, pSumsqs + 4*Hc, bn5_g, bn5_b, 1.f / 6144.f,
        pZero, pAct, (float*)pMf, nullptr, nullptr,
        384, 1, 1, 384, 384, 512, Hc * T3c, Hc * T3c, Kbot);

    // bottleneck: tensor-core fp16x3 (g_h zeroed by prep)
    bottleneck_tc<<<dim3(8, 64), 256>>>(bot_w);

    // fused bn2d + embedding + norm
    emb_fused<<<16, 512>>>(bot_b, bnb_g, bnb_b, emb_w, emb_b, out);
}